// round 2
// baseline (speedup 1.0000x reference)
#include <cuda_runtime.h>
#include <cuda_bf16.h>

// ---------------- static problem configuration ----------------
#define TOTAL    6848
#define D_MODEL  768
#define D_INNER  1536
#define D_STATE  16
#define DT_RANK  48
#define NSUBJ    8
#define N_LAYERS 2
#define EPS      1e-5f

__constant__ int c_offsets[NSUBJ + 1] = {0, 1024, 1920, 2688, 3712, 4224, 4864, 5824, 6848};

// ---------------- scratch (device globals; no runtime allocation) ----------------
__device__ float g_h  [TOTAL * D_MODEL];        // residual stream
__device__ float g_hn [TOTAL * D_MODEL];        // rmsnorm(h)
__device__ float g_xz [TOTAL * 2 * D_INNER];    // in_proj output (x | z)
__device__ float g_xc [TOTAL * D_INNER];        // conv+silu output
__device__ float g_dbl[TOTAL * 80];             // x_proj output (dt_r | B | C)
__device__ float g_dt [TOTAL * D_INNER];        // softplus(dt_proj)
__device__ float g_y  [TOTAL * D_INNER];        // scan output * silu(z)

// ---------------- helpers ----------------
__device__ __forceinline__ float blockReduceSum(float v) {
    __shared__ float sh[8];
    __shared__ float total;
    #pragma unroll
    for (int o = 16; o; o >>= 1) v += __shfl_xor_sync(0xffffffffu, v, o);
    if ((threadIdx.x & 31) == 0) sh[threadIdx.x >> 5] = v;
    __syncthreads();
    v = (threadIdx.x < 8) ? sh[threadIdx.x] : 0.f;
    #pragma unroll
    for (int o = 4; o; o >>= 1) v += __shfl_xor_sync(0xffffffffu, v, o);
    if (threadIdx.x == 0) total = v;
    __syncthreads();
    return total;
}

__device__ __forceinline__ float silu_f(float x) {
    return x / (1.f + __expf(-x));
}

// ---------------- embed gather + rmsnorm ----------------
__global__ void __launch_bounds__(256) embed_rms_kernel(
    const int* __restrict__ tokens, const float* __restrict__ embed,
    const float* __restrict__ w, float* __restrict__ out)
{
    const int row = blockIdx.x;
    const float* xr = embed + (size_t)tokens[row] * D_MODEL;
    float s = 0.f;
    for (int i = threadIdx.x; i < D_MODEL; i += 256) { float v = xr[i]; s += v * v; }
    float tot = blockReduceSum(s);
    float r = rsqrtf(tot / D_MODEL + EPS);
    for (int i = threadIdx.x; i < D_MODEL; i += 256)
        out[row * D_MODEL + i] = xr[i] * r * w[i];
}

// ---------------- rmsnorm ----------------
__global__ void __launch_bounds__(256) rms_kernel(
    const float* __restrict__ x, const float* __restrict__ w, float* __restrict__ out)
{
    const int row = blockIdx.x;
    const float* xr = x + row * D_MODEL;
    float s = 0.f;
    for (int i = threadIdx.x; i < D_MODEL; i += 256) { float v = xr[i]; s += v * v; }
    float tot = blockReduceSum(s);
    float r = rsqrtf(tot / D_MODEL + EPS);
    for (int i = threadIdx.x; i < D_MODEL; i += 256)
        out[row * D_MODEL + i] = xr[i] * r * w[i];
}

// ---------------- final: rmsnorm(norm_f) then rmsnorm(out_norm) ----------------
__global__ void __launch_bounds__(256) final_kernel(
    const float* __restrict__ x, const float* __restrict__ wf,
    const float* __restrict__ wo, float* __restrict__ out)
{
    const int row = blockIdx.x;
    const float* xr = x + row * D_MODEL;
    float s1 = 0.f, s2 = 0.f;
    for (int i = threadIdx.x; i < D_MODEL; i += 256) {
        float v = xr[i];
        float vw = v * wf[i];
        s1 += v * v;
        s2 += vw * vw;
    }
    float t1 = blockReduceSum(s1);
    float t2 = blockReduceSum(s2);
    float r1 = rsqrtf(t1 / D_MODEL + EPS);
    float m2 = (r1 * r1) * t2 / D_MODEL;
    float r2 = rsqrtf(m2 + EPS);
    for (int i = threadIdx.x; i < D_MODEL; i += 256)
        out[row * D_MODEL + i] = xr[i] * wf[i] * r1 * r2 * wo[i];
}

// ---------------- GEMM: C[M,N] (op) A[M,K](lda) * W[N,K]^T ----------------
// epi: 0 = store, 1 = softplus(acc + bias[n]), 2 = C += acc (residual accumulate)
// BM=64, BN=128, BK=16, 256 threads, 4x8 micro-tile. M = TOTAL (multiple of 64).
__global__ void __launch_bounds__(256) gemm_kernel(
    const float* __restrict__ A, const float* __restrict__ W,
    const float* __restrict__ bias, float* __restrict__ C,
    int N, int K, int lda, int epi)
{
    const int m0 = blockIdx.y * 64;
    const int n0 = blockIdx.x * 128;
    const int tid = threadIdx.x;
    const int ty = tid >> 4;     // 0..15  (rows)
    const int tx = tid & 15;     // 0..15  (cols)

    __shared__ float As[16][64];
    __shared__ float Ws[16][128];

    float acc[4][8];
    #pragma unroll
    for (int i = 0; i < 4; i++)
        #pragma unroll
        for (int j = 0; j < 8; j++) acc[i][j] = 0.f;

    const int arow = tid >> 2;            // 0..63
    const int ak   = (tid & 3) << 2;      // 0,4,8,12
    const int wrow = tid >> 1;            // 0..127
    const int wk   = (tid & 1) << 3;      // 0,8
    const bool wvalid = (n0 + wrow) < N;

    for (int k0 = 0; k0 < K; k0 += 16) {
        float4 av = *(const float4*)(A + (size_t)(m0 + arow) * lda + k0 + ak);
        As[ak + 0][arow] = av.x; As[ak + 1][arow] = av.y;
        As[ak + 2][arow] = av.z; As[ak + 3][arow] = av.w;

        if (wvalid) {
            const float* wp = W + (size_t)(n0 + wrow) * K + k0 + wk;
            float4 w0 = *(const float4*)(wp);
            float4 w1 = *(const float4*)(wp + 4);
            Ws[wk + 0][wrow] = w0.x; Ws[wk + 1][wrow] = w0.y;
            Ws[wk + 2][wrow] = w0.z; Ws[wk + 3][wrow] = w0.w;
            Ws[wk + 4][wrow] = w1.x; Ws[wk + 5][wrow] = w1.y;
            Ws[wk + 6][wrow] = w1.z; Ws[wk + 7][wrow] = w1.w;
        } else {
            #pragma unroll
            for (int j = 0; j < 8; j++) Ws[wk + j][wrow] = 0.f;
        }
        __syncthreads();

        #pragma unroll
        for (int kk = 0; kk < 16; kk++) {
            float4 a4 = *(const float4*)&As[kk][ty * 4];
            float4 b0 = *(const float4*)&Ws[kk][tx * 8];
            float4 b1 = *(const float4*)&Ws[kk][tx * 8 + 4];
            float ar[4] = {a4.x, a4.y, a4.z, a4.w};
            float br[8] = {b0.x, b0.y, b0.z, b0.w, b1.x, b1.y, b1.z, b1.w};
            #pragma unroll
            for (int i = 0; i < 4; i++)
                #pragma unroll
                for (int j = 0; j < 8; j++)
                    acc[i][j] = fmaf(ar[i], br[j], acc[i][j]);
        }
        __syncthreads();
    }

    #pragma unroll
    for (int i = 0; i < 4; i++) {
        int m = m0 + ty * 4 + i;
        size_t rb = (size_t)m * N;
        #pragma unroll
        for (int j = 0; j < 8; j++) {
            int n = n0 + tx * 8 + j;
            if (n < N) {
                float v = acc[i][j];
                if (epi == 1) {
                    v += bias[n];
                    v = (v > 20.f) ? v : log1pf(__expf(v));
                    C[rb + n] = v;
                } else if (epi == 2) {
                    C[rb + n] += v;
                } else {
                    C[rb + n] = v;
                }
            }
        }
    }
}

// ---------------- causal depthwise conv (k=4) + bias + silu ----------------
__global__ void __launch_bounds__(256) conv_kernel(
    const float* __restrict__ xz, const float* __restrict__ cw,
    const float* __restrict__ cb, float* __restrict__ xc)
{
    int idx = blockIdx.x * 256 + threadIdx.x;
    if (idx >= TOTAL * D_INNER) return;
    int t = idx / D_INNER;
    int i = idx - t * D_INNER;
    int t0 = 0;
    #pragma unroll
    for (int s = 1; s < NSUBJ; s++)
        if (t >= c_offsets[s]) t0 = c_offsets[s];

    float w0 = cw[i * 4 + 0], w1 = cw[i * 4 + 1], w2 = cw[i * 4 + 2], w3 = cw[i * 4 + 3];
    float acc = cb[i] + w3 * xz[(size_t)t * (2 * D_INNER) + i];
    if (t - 1 >= t0) acc = fmaf(w2, xz[(size_t)(t - 1) * (2 * D_INNER) + i], acc);
    if (t - 2 >= t0) acc = fmaf(w1, xz[(size_t)(t - 2) * (2 * D_INNER) + i], acc);
    if (t - 3 >= t0) acc = fmaf(w0, xz[(size_t)(t - 3) * (2 * D_INNER) + i], acc);
    xc[idx] = silu_f(acc);
}

// ---------------- selective scan (+ D skip + silu(z) gate) ----------------
// grid: (D_INNER/16, NSUBJ), 256 threads. lane: dl = tid>>4 (channel within
// 16-chan block), n = tid&15 (state). One lane per (channel, state).
__global__ void __launch_bounds__(256) scan_kernel(
    const float* __restrict__ xc, const float* __restrict__ dt,
    const float* __restrict__ dbl, const float* __restrict__ xz,
    const float* __restrict__ A_log, const float* __restrict__ Dp,
    float* __restrict__ y)
{
    const int subj = blockIdx.y;
    const int d0 = blockIdx.x * 16;
    const int off = c_offsets[subj];
    const int L = c_offsets[subj + 1] - off;
    const int tid = threadIdx.x;
    const int dl = tid >> 4;
    const int n  = tid & 15;
    const int d  = d0 + dl;

    const float Acoef = -__expf(A_log[d * D_STATE + n]);
    const float Dv = Dp[d];
    float hc = 0.f;

    __shared__ float sh_dt[64][16], sh_x[64][16], sh_z[64][16], sh_B[64][16], sh_C[64][16];

    for (int tb = 0; tb < L; tb += 64) {
        int nsteps = min(64, L - tb);
        for (int idx = tid; idx < 64 * 16; idx += 256) {
            int tl = idx >> 4, dd = idx & 15;
            if (tl < nsteps) {
                int t = off + tb + tl;
                sh_dt[tl][dd] = dt[(size_t)t * D_INNER + d0 + dd];
                sh_x [tl][dd] = xc[(size_t)t * D_INNER + d0 + dd];
                sh_z [tl][dd] = xz[(size_t)t * (2 * D_INNER) + D_INNER + d0 + dd];
                sh_B [tl][dd] = dbl[(size_t)t * 80 + DT_RANK + dd];
                sh_C [tl][dd] = dbl[(size_t)t * 80 + DT_RANK + D_STATE + dd];
            }
        }
        __syncthreads();
        for (int s = 0; s < nsteps; s++) {
            float dtv = sh_dt[s][dl];
            float xv  = sh_x[s][dl];
            float dA = __expf(dtv * Acoef);
            hc = fmaf(dA, hc, (dtv * xv) * sh_B[s][n]);
            float p = hc * sh_C[s][n];
            p += __shfl_xor_sync(0xffffffffu, p, 1);
            p += __shfl_xor_sync(0xffffffffu, p, 2);
            p += __shfl_xor_sync(0xffffffffu, p, 4);
            p += __shfl_xor_sync(0xffffffffu, p, 8);
            if (n == 0) {
                float yv = p + xv * Dv;
                float zv = sh_z[s][dl];
                yv *= silu_f(zv);
                y[(size_t)(off + tb + s) * D_INNER + d] = yv;
            }
        }
        __syncthreads();
    }
}

// ---------------- launch ----------------
extern "C" void kernel_launch(void* const* d_in, const int* in_sizes, int n_in,
                              void* d_out, int out_size) {
    const int*   tokens     = (const int*)  d_in[0];
    const float* embed      = (const float*)d_in[1];
    const float* in_norm_w  = (const float*)d_in[2];
    const float* out_norm_w = (const float*)d_in[3];
    const float* norm_w     = (const float*)d_in[4];
    const float* in_proj_w  = (const float*)d_in[5];
    const float* conv_w     = (const float*)d_in[6];
    const float* conv_b     = (const float*)d_in[7];
    const float* x_proj_w   = (const float*)d_in[8];
    const float* dt_proj_w  = (const float*)d_in[9];
    const float* dt_proj_b  = (const float*)d_in[10];
    const float* A_log      = (const float*)d_in[11];
    const float* D_param    = (const float*)d_in[12];
    const float* out_proj_w = (const float*)d_in[13];
    const float* norm_f_w   = (const float*)d_in[14];
    float* out = (float*)d_out;

    float *h, *hn, *xz, *xc, *dbl, *dt, *y;
    cudaGetSymbolAddress((void**)&h,   g_h);
    cudaGetSymbolAddress((void**)&hn,  g_hn);
    cudaGetSymbolAddress((void**)&xz,  g_xz);
    cudaGetSymbolAddress((void**)&xc,  g_xc);
    cudaGetSymbolAddress((void**)&dbl, g_dbl);
    cudaGetSymbolAddress((void**)&dt,  g_dt);
    cudaGetSymbolAddress((void**)&y,   g_y);

    const int MB = TOTAL / 64;  // 107

    embed_rms_kernel<<<TOTAL, 256>>>(tokens, embed, in_norm_w, h);

    for (int l = 0; l < N_LAYERS; l++) {
        rms_kernel<<<TOTAL, 256>>>(h, norm_w + l * D_MODEL, hn);

        // xz = hn @ in_proj_w^T   [TOTAL, 3072]
        gemm_kernel<<<dim3(2 * D_INNER / 128, MB), 256>>>(
            hn, in_proj_w + (size_t)l * 2 * D_INNER * D_MODEL, nullptr, xz,
            2 * D_INNER, D_MODEL, D_MODEL, 0);

        conv_kernel<<<(TOTAL * D_INNER + 255) / 256, 256>>>(
            xz, conv_w + (size_t)l * D_INNER * 4, conv_b + (size_t)l * D_INNER, xc);

        // dbl = xc @ x_proj_w^T   [TOTAL, 80]
        gemm_kernel<<<dim3(1, MB), 256>>>(
            xc, x_proj_w + (size_t)l * 80 * D_INNER, nullptr, dbl,
            80, D_INNER, D_INNER, 0);

        // dt = softplus(dbl[:, :48] @ dt_proj_w^T + b)   [TOTAL, 1536]
        gemm_kernel<<<dim3(D_INNER / 128, MB), 256>>>(
            dbl, dt_proj_w + (size_t)l * D_INNER * DT_RANK,
            dt_proj_b + (size_t)l * D_INNER, dt,
            D_INNER, DT_RANK, 80, 1);

        scan_kernel<<<dim3(D_INNER / 16, NSUBJ), 256>>>(
            xc, dt, dbl, xz,
            A_log + (size_t)l * D_INNER * D_STATE, D_param + (size_t)l * D_INNER, y);

        // h += y @ out_proj_w^T   [TOTAL, 768]
        gemm_kernel<<<dim3(D_MODEL / 128, MB), 256>>>(
            y, out_proj_w + (size_t)l * D_MODEL * D_INNER, nullptr, h,
            D_MODEL, D_INNER, D_INNER, 2);
    }

    final_kernel<<<TOTAL, 256>>>(h, norm_f_w, out_norm_w, out);
}

// round 3
// speedup vs baseline: 1.5458x; 1.5458x over previous
#include <cuda_runtime.h>
#include <cuda_bf16.h>
#include <cstdint>

// ---------------- static problem configuration ----------------
#define TOTAL    6848
#define D_MODEL  768
#define D_INNER  1536
#define D_STATE  16
#define DT_RANK  48
#define NSUBJ    8
#define N_LAYERS 2
#define EPS      1e-5f

__constant__ int c_offsets[NSUBJ + 1] = {0, 1024, 1920, 2688, 3712, 4224, 4864, 5824, 6848};

// ---------------- scratch (device globals; no runtime allocation) ----------------
__device__ float g_h  [TOTAL * D_MODEL];
__device__ float g_hn [TOTAL * D_MODEL];
__device__ float g_xz [TOTAL * 2 * D_INNER];
__device__ float g_xc [TOTAL * D_INNER];
__device__ float g_dbl[TOTAL * 80];
__device__ float g_dt [TOTAL * D_INNER];
__device__ float g_y  [TOTAL * D_INNER];

// ---------------- helpers ----------------
__device__ __forceinline__ float blockReduceSum(float v) {
    __shared__ float sh[8];
    __shared__ float total;
    #pragma unroll
    for (int o = 16; o; o >>= 1) v += __shfl_xor_sync(0xffffffffu, v, o);
    if ((threadIdx.x & 31) == 0) sh[threadIdx.x >> 5] = v;
    __syncthreads();
    v = (threadIdx.x < 8) ? sh[threadIdx.x] : 0.f;
    #pragma unroll
    for (int o = 4; o; o >>= 1) v += __shfl_xor_sync(0xffffffffu, v, o);
    if (threadIdx.x == 0) total = v;
    __syncthreads();
    return total;
}

__device__ __forceinline__ float silu_f(float x) {
    return x / (1.f + __expf(-x));
}

// split fp32 pair into hi/lo bf16x2 words
__device__ __forceinline__ void split2(float f0, float f1, uint32_t& hi, uint32_t& lo) {
    __nv_bfloat162 h = __floats2bfloat162_rn(f0, f1);
    float r0 = f0 - __bfloat162float(h.x);
    float r1 = f1 - __bfloat162float(h.y);
    __nv_bfloat162 l = __floats2bfloat162_rn(r0, r1);
    hi = *reinterpret_cast<uint32_t*>(&h);
    lo = *reinterpret_cast<uint32_t*>(&l);
}

__device__ __forceinline__ void mma_bf16(float* c, const uint32_t* a, uint32_t b0, uint32_t b1) {
    asm volatile(
        "mma.sync.aligned.m16n8k16.row.col.f32.bf16.bf16.f32 "
        "{%0,%1,%2,%3}, {%4,%5,%6,%7}, {%8,%9}, {%0,%1,%2,%3};"
        : "+f"(c[0]), "+f"(c[1]), "+f"(c[2]), "+f"(c[3])
        : "r"(a[0]), "r"(a[1]), "r"(a[2]), "r"(a[3]), "r"(b0), "r"(b1));
}

// ---------------- embed gather + rmsnorm ----------------
__global__ void __launch_bounds__(256) embed_rms_kernel(
    const int* __restrict__ tokens, const float* __restrict__ embed,
    const float* __restrict__ w, float* __restrict__ out)
{
    const int row = blockIdx.x;
    const float* xr = embed + (size_t)tokens[row] * D_MODEL;
    float s = 0.f;
    for (int i = threadIdx.x; i < D_MODEL; i += 256) { float v = xr[i]; s += v * v; }
    float tot = blockReduceSum(s);
    float r = rsqrtf(tot / D_MODEL + EPS);
    for (int i = threadIdx.x; i < D_MODEL; i += 256)
        out[row * D_MODEL + i] = xr[i] * r * w[i];
}

// ---------------- rmsnorm ----------------
__global__ void __launch_bounds__(256) rms_kernel(
    const float* __restrict__ x, const float* __restrict__ w, float* __restrict__ out)
{
    const int row = blockIdx.x;
    const float* xr = x + row * D_MODEL;
    float s = 0.f;
    for (int i = threadIdx.x; i < D_MODEL; i += 256) { float v = xr[i]; s += v * v; }
    float tot = blockReduceSum(s);
    float r = rsqrtf(tot / D_MODEL + EPS);
    for (int i = threadIdx.x; i < D_MODEL; i += 256)
        out[row * D_MODEL + i] = xr[i] * r * w[i];
}

// ---------------- final: rmsnorm(norm_f) then rmsnorm(out_norm) ----------------
__global__ void __launch_bounds__(256) final_kernel(
    const float* __restrict__ x, const float* __restrict__ wf,
    const float* __restrict__ wo, float* __restrict__ out)
{
    const int row = blockIdx.x;
    const float* xr = x + row * D_MODEL;
    float s1 = 0.f, s2 = 0.f;
    for (int i = threadIdx.x; i < D_MODEL; i += 256) {
        float v = xr[i];
        float vw = v * wf[i];
        s1 += v * v;
        s2 += vw * vw;
    }
    float t1 = blockReduceSum(s1);
    float t2 = blockReduceSum(s2);
    float r1 = rsqrtf(t1 / D_MODEL + EPS);
    float m2 = (r1 * r1) * t2 / D_MODEL;
    float r2 = rsqrtf(m2 + EPS);
    for (int i = threadIdx.x; i < D_MODEL; i += 256)
        out[row * D_MODEL + i] = xr[i] * wf[i] * r1 * r2 * wo[i];
}

// ---------------- tensor-core GEMM: C[M,N] (op)= A[M,K](lda) * W[N,K]^T ----------------
// Split-bf16: fp32 = hi(bf16) + lo(bf16); C = Ah*Bh + Ah*Bl + Al*Bh (fp32 acc).
// Block 128x128x32, 8 warps (2x4), warp tile 64x32, mma m16n8k16.
// epi: 0 = store, 1 = softplus(acc + bias[n]), 2 = C += acc
__global__ void __launch_bounds__(256, 2) gemm_tc_kernel(
    const float* __restrict__ A, const float* __restrict__ W,
    const float* __restrict__ bias, float* __restrict__ C,
    int M, int N, int K, int lda, int epi)
{
    __shared__ uint32_t As_hi[16 * 128], As_lo[16 * 128];
    __shared__ uint32_t Bs_hi[16 * 128], Bs_lo[16 * 128];

    const int tid  = threadIdx.x;
    const int m0   = blockIdx.y * 128;
    const int n0   = blockIdx.x * 128;
    const int warp = tid >> 5, lane = tid & 31;
    const int wm   = (warp & 1) * 64;   // warp m offset
    const int wn   = (warp >> 1) * 32;  // warp n offset
    const int g    = lane >> 2, tg = lane & 3;

    float acc[4][4][4];
    #pragma unroll
    for (int mi = 0; mi < 4; mi++)
        #pragma unroll
        for (int ni = 0; ni < 4; ni++)
            #pragma unroll
            for (int r = 0; r < 4; r++) acc[mi][ni][r] = 0.f;

    for (int k0 = 0; k0 < K; k0 += 32) {
        // ---- load 128x32 fp32 tiles of A and W, split to bf16 hi/lo in smem ----
        #pragma unroll
        for (int p = 0; p < 4; p++) {
            int li  = p * 256 + tid;       // float4 index 0..1023
            int row = li >> 3;             // 0..127
            int q   = li & 7;              // float4 column 0..7
            int k   = k0 + q * 4;
            int kp0 = q * 2, kp1 = q * 2 + 1;
            int ia0 = kp0 * 128 + (row ^ ((kp0 & 3) << 3));
            int ia1 = kp1 * 128 + (row ^ ((kp1 & 3) << 3));

            // A
            float4 va = make_float4(0.f, 0.f, 0.f, 0.f);
            int ar = m0 + row; if (ar >= M) ar = M - 1;
            const float* ap = A + (size_t)ar * lda;
            if (k + 3 < K) {
                va = *(const float4*)(ap + k);
            } else {
                if (k     < K) va.x = ap[k];
                if (k + 1 < K) va.y = ap[k + 1];
                if (k + 2 < K) va.z = ap[k + 2];
                if (k + 3 < K) va.w = ap[k + 3];
            }
            uint32_t h0, l0, h1, l1;
            split2(va.x, va.y, h0, l0);
            split2(va.z, va.w, h1, l1);
            As_hi[ia0] = h0; As_lo[ia0] = l0;
            As_hi[ia1] = h1; As_lo[ia1] = l1;

            // B (= W row n0+row)
            float4 vb = make_float4(0.f, 0.f, 0.f, 0.f);
            int br = n0 + row;
            if (br < N) {
                const float* wp = W + (size_t)br * K;
                if (k + 3 < K) {
                    vb = *(const float4*)(wp + k);
                } else {
                    if (k     < K) vb.x = wp[k];
                    if (k + 1 < K) vb.y = wp[k + 1];
                    if (k + 2 < K) vb.z = wp[k + 2];
                    if (k + 3 < K) vb.w = wp[k + 3];
                }
            }
            split2(vb.x, vb.y, h0, l0);
            split2(vb.z, vb.w, h1, l1);
            Bs_hi[ia0] = h0; Bs_lo[ia0] = l0;
            Bs_hi[ia1] = h1; Bs_lo[ia1] = l1;
        }
        __syncthreads();

        // ---- compute: 2 k-steps of 16 ----
        #pragma unroll
        for (int s = 0; s < 2; s++) {
            const int kpA = s * 8 + tg;
            const int kpB = s * 8 + tg + 4;
            const int swA = (kpA & 3) << 3;
            const int swB = (kpB & 3) << 3;

            uint32_t a_hi[4][4], a_lo[4][4];
            #pragma unroll
            for (int mi = 0; mi < 4; mi++) {
                int mb = wm + mi * 16;
                int i0 = kpA * 128 + ((mb + g)     ^ swA);
                int i1 = kpA * 128 + ((mb + g + 8) ^ swA);
                int i2 = kpB * 128 + ((mb + g)     ^ swB);
                int i3 = kpB * 128 + ((mb + g + 8) ^ swB);
                a_hi[mi][0] = As_hi[i0]; a_hi[mi][1] = As_hi[i1];
                a_hi[mi][2] = As_hi[i2]; a_hi[mi][3] = As_hi[i3];
                a_lo[mi][0] = As_lo[i0]; a_lo[mi][1] = As_lo[i1];
                a_lo[mi][2] = As_lo[i2]; a_lo[mi][3] = As_lo[i3];
            }
            #pragma unroll
            for (int ni = 0; ni < 4; ni++) {
                int nb = wn + ni * 8 + g;
                int j0 = kpA * 128 + (nb ^ swA);
                int j1 = kpB * 128 + (nb ^ swB);
                uint32_t bh0 = Bs_hi[j0], bh1 = Bs_hi[j1];
                uint32_t bl0 = Bs_lo[j0], bl1 = Bs_lo[j1];
                #pragma unroll
                for (int mi = 0; mi < 4; mi++) {
                    mma_bf16(acc[mi][ni], a_hi[mi], bh0, bh1);
                    mma_bf16(acc[mi][ni], a_hi[mi], bl0, bl1);
                    mma_bf16(acc[mi][ni], a_lo[mi], bh0, bh1);
                }
            }
        }
        __syncthreads();
    }

    // ---- epilogue ----
    #pragma unroll
    for (int mi = 0; mi < 4; mi++) {
        int mrow0 = m0 + wm + mi * 16 + g;
        int mrow1 = mrow0 + 8;
        #pragma unroll
        for (int ni = 0; ni < 4; ni++) {
            int n = n0 + wn + ni * 8 + 2 * tg;
            if (n >= N) continue;   // N is a multiple of 8 -> pair-safe
            float* c = acc[mi][ni];
            if (epi == 1) {
                float b0 = bias[n], b1 = bias[n + 1];
                #pragma unroll
                for (int r = 0; r < 4; r++) {
                    float v = c[r] + ((r & 1) ? b1 : b0);
                    c[r] = (v > 20.f) ? v : log1pf(__expf(v));
                }
            }
            if (mrow0 < M) {
                size_t b = (size_t)mrow0 * N + n;
                if (epi == 2) { C[b] += c[0]; C[b + 1] += c[1]; }
                else          { C[b]  = c[0]; C[b + 1]  = c[1]; }
            }
            if (mrow1 < M) {
                size_t b = (size_t)mrow1 * N + n;
                if (epi == 2) { C[b] += c[2]; C[b + 1] += c[3]; }
                else          { C[b]  = c[2]; C[b + 1]  = c[3]; }
            }
        }
    }
}

// ---------------- causal depthwise conv (k=4) + bias + silu ----------------
__global__ void __launch_bounds__(256) conv_kernel(
    const float* __restrict__ xz, const float* __restrict__ cw,
    const float* __restrict__ cb, float* __restrict__ xc)
{
    int idx = blockIdx.x * 256 + threadIdx.x;
    if (idx >= TOTAL * D_INNER) return;
    int t = idx / D_INNER;
    int i = idx - t * D_INNER;
    int t0 = 0;
    #pragma unroll
    for (int s = 1; s < NSUBJ; s++)
        if (t >= c_offsets[s]) t0 = c_offsets[s];

    float w0 = cw[i * 4 + 0], w1 = cw[i * 4 + 1], w2 = cw[i * 4 + 2], w3 = cw[i * 4 + 3];
    float acc = cb[i] + w3 * xz[(size_t)t * (2 * D_INNER) + i];
    if (t - 1 >= t0) acc = fmaf(w2, xz[(size_t)(t - 1) * (2 * D_INNER) + i], acc);
    if (t - 2 >= t0) acc = fmaf(w1, xz[(size_t)(t - 2) * (2 * D_INNER) + i], acc);
    if (t - 3 >= t0) acc = fmaf(w0, xz[(size_t)(t - 3) * (2 * D_INNER) + i], acc);
    xc[idx] = silu_f(acc);
}

// ---------------- selective scan (+ D skip + silu(z) gate) ----------------
__global__ void __launch_bounds__(256) scan_kernel(
    const float* __restrict__ xc, const float* __restrict__ dt,
    const float* __restrict__ dbl, const float* __restrict__ xz,
    const float* __restrict__ A_log, const float* __restrict__ Dp,
    float* __restrict__ y)
{
    const int subj = blockIdx.y;
    const int d0 = blockIdx.x * 16;
    const int off = c_offsets[subj];
    const int L = c_offsets[subj + 1] - off;
    const int tid = threadIdx.x;
    const int dl = tid >> 4;
    const int n  = tid & 15;
    const int d  = d0 + dl;

    const float Acoef = -__expf(A_log[d * D_STATE + n]);
    const float Dv = Dp[d];
    float hc = 0.f;

    __shared__ float sh_dt[64][16], sh_x[64][16], sh_z[64][16], sh_B[64][16], sh_C[64][16];

    for (int tb = 0; tb < L; tb += 64) {
        int nsteps = min(64, L - tb);
        for (int idx = tid; idx < 64 * 16; idx += 256) {
            int tl = idx >> 4, dd = idx & 15;
            if (tl < nsteps) {
                int t = off + tb + tl;
                sh_dt[tl][dd] = dt[(size_t)t * D_INNER + d0 + dd];
                sh_x [tl][dd] = xc[(size_t)t * D_INNER + d0 + dd];
                sh_z [tl][dd] = xz[(size_t)t * (2 * D_INNER) + D_INNER + d0 + dd];
                sh_B [tl][dd] = dbl[(size_t)t * 80 + DT_RANK + dd];
                sh_C [tl][dd] = dbl[(size_t)t * 80 + DT_RANK + D_STATE + dd];
            }
        }
        __syncthreads();
        for (int s = 0; s < nsteps; s++) {
            float dtv = sh_dt[s][dl];
            float xv  = sh_x[s][dl];
            float dA = __expf(dtv * Acoef);
            hc = fmaf(dA, hc, (dtv * xv) * sh_B[s][n]);
            float p = hc * sh_C[s][n];
            p += __shfl_xor_sync(0xffffffffu, p, 1);
            p += __shfl_xor_sync(0xffffffffu, p, 2);
            p += __shfl_xor_sync(0xffffffffu, p, 4);
            p += __shfl_xor_sync(0xffffffffu, p, 8);
            if (n == 0) {
                float yv = p + xv * Dv;
                float zv = sh_z[s][dl];
                yv *= silu_f(zv);
                y[(size_t)(off + tb + s) * D_INNER + d] = yv;
            }
        }
        __syncthreads();
    }
}

// ---------------- launch ----------------
extern "C" void kernel_launch(void* const* d_in, const int* in_sizes, int n_in,
                              void* d_out, int out_size) {
    const int*   tokens     = (const int*)  d_in[0];
    const float* embed      = (const float*)d_in[1];
    const float* in_norm_w  = (const float*)d_in[2];
    const float* out_norm_w = (const float*)d_in[3];
    const float* norm_w     = (const float*)d_in[4];
    const float* in_proj_w  = (const float*)d_in[5];
    const float* conv_w     = (const float*)d_in[6];
    const float* conv_b     = (const float*)d_in[7];
    const float* x_proj_w   = (const float*)d_in[8];
    const float* dt_proj_w  = (const float*)d_in[9];
    const float* dt_proj_b  = (const float*)d_in[10];
    const float* A_log      = (const float*)d_in[11];
    const float* D_param    = (const float*)d_in[12];
    const float* out_proj_w = (const float*)d_in[13];
    const float* norm_f_w   = (const float*)d_in[14];
    float* out = (float*)d_out;

    float *h, *hn, *xz, *xc, *dbl, *dt, *y;
    cudaGetSymbolAddress((void**)&h,   g_h);
    cudaGetSymbolAddress((void**)&hn,  g_hn);
    cudaGetSymbolAddress((void**)&xz,  g_xz);
    cudaGetSymbolAddress((void**)&xc,  g_xc);
    cudaGetSymbolAddress((void**)&dbl, g_dbl);
    cudaGetSymbolAddress((void**)&dt,  g_dt);
    cudaGetSymbolAddress((void**)&y,   g_y);

    const int MB = (TOTAL + 127) / 128;  // 54

    embed_rms_kernel<<<TOTAL, 256>>>(tokens, embed, in_norm_w, h);

    for (int l = 0; l < N_LAYERS; l++) {
        rms_kernel<<<TOTAL, 256>>>(h, norm_w + l * D_MODEL, hn);

        // xz = hn @ in_proj_w^T   [TOTAL, 3072]
        gemm_tc_kernel<<<dim3(2 * D_INNER / 128, MB), 256>>>(
            hn, in_proj_w + (size_t)l * 2 * D_INNER * D_MODEL, nullptr, xz,
            TOTAL, 2 * D_INNER, D_MODEL, D_MODEL, 0);

        conv_kernel<<<(TOTAL * D_INNER + 255) / 256, 256>>>(
            xz, conv_w + (size_t)l * D_INNER * 4, conv_b + (size_t)l * D_INNER, xc);

        // dbl = xc @ x_proj_w^T   [TOTAL, 80]
        gemm_tc_kernel<<<dim3(1, MB), 256>>>(
            xc, x_proj_w + (size_t)l * 80 * D_INNER, nullptr, dbl,
            TOTAL, 80, D_INNER, D_INNER, 0);

        // dt = softplus(dbl[:, :48] @ dt_proj_w^T + b)   [TOTAL, 1536]
        gemm_tc_kernel<<<dim3(D_INNER / 128, MB), 256>>>(
            dbl, dt_proj_w + (size_t)l * D_INNER * DT_RANK,
            dt_proj_b + (size_t)l * D_INNER, dt,
            TOTAL, D_INNER, DT_RANK, 80, 1);

        scan_kernel<<<dim3(D_INNER / 16, NSUBJ), 256>>>(
            xc, dt, dbl, xz,
            A_log + (size_t)l * D_INNER * D_STATE, D_param + (size_t)l * D_INNER, y);

        // h += y @ out_proj_w^T   [TOTAL, 768]
        gemm_tc_kernel<<<dim3(D_MODEL / 128, MB), 256>>>(
            y, out_proj_w + (size_t)l * D_MODEL * D_INNER, nullptr, h,
            TOTAL, D_MODEL, D_INNER, D_INNER, 2);
    }

    final_kernel<<<TOTAL, 256>>>(h, norm_f_w, out_norm_w, out);
}

// round 4
// speedup vs baseline: 2.4117x; 1.5602x over previous
#include <cuda_runtime.h>
#include <cuda_bf16.h>
#include <cstdint>

// ---------------- static problem configuration ----------------
#define TOTAL    6848
#define D_MODEL  768
#define D_INNER  1536
#define D_STATE  16
#define DT_RANK  48
#define NSUBJ    8
#define N_LAYERS 2
#define EPS      1e-5f

__constant__ int c_offsets[NSUBJ + 1] = {0, 1024, 1920, 2688, 3712, 4224, 4864, 5824, 6848};

// per-layer weight element counts
#define IPW_N (2 * D_INNER * D_MODEL)      // 2359296
#define XPW_N ((DT_RANK + 2 * D_STATE) * D_INNER)  // 122880
#define DTW_N (D_INNER * DT_RANK)          // 73728
#define OPW_N (D_MODEL * D_INNER)          // 1179648

// ---------------- scratch (device globals; no runtime allocation) ----------------
__device__ float g_h  [TOTAL * D_MODEL];
__device__ float g_xz [TOTAL * 2 * D_INNER];
__device__ float g_xc [TOTAL * D_INNER];
__device__ float g_dbl[TOTAL * 80];
__device__ float g_dt [TOTAL * D_INNER];

__device__ __nv_bfloat16 g_hn_hi[TOTAL * D_MODEL],  g_hn_lo[TOTAL * D_MODEL];
__device__ __nv_bfloat16 g_xc_hi[TOTAL * D_INNER],  g_xc_lo[TOTAL * D_INNER];
__device__ __nv_bfloat16 g_db_hi[TOTAL * DT_RANK],  g_db_lo[TOTAL * DT_RANK];
__device__ __nv_bfloat16 g_y_hi [TOTAL * D_INNER],  g_y_lo [TOTAL * D_INNER];

__device__ __nv_bfloat16 g_ip_hi[N_LAYERS * IPW_N], g_ip_lo[N_LAYERS * IPW_N];
__device__ __nv_bfloat16 g_xp_hi[N_LAYERS * XPW_N], g_xp_lo[N_LAYERS * XPW_N];
__device__ __nv_bfloat16 g_dw_hi[N_LAYERS * DTW_N], g_dw_lo[N_LAYERS * DTW_N];
__device__ __nv_bfloat16 g_op_hi[N_LAYERS * OPW_N], g_op_lo[N_LAYERS * OPW_N];

// ---------------- helpers ----------------
__device__ __forceinline__ float blockReduceSum(float v) {
    __shared__ float sh[8];
    __shared__ float total;
    #pragma unroll
    for (int o = 16; o; o >>= 1) v += __shfl_xor_sync(0xffffffffu, v, o);
    if ((threadIdx.x & 31) == 0) sh[threadIdx.x >> 5] = v;
    __syncthreads();
    v = (threadIdx.x < 8) ? sh[threadIdx.x] : 0.f;
    #pragma unroll
    for (int o = 4; o; o >>= 1) v += __shfl_xor_sync(0xffffffffu, v, o);
    if (threadIdx.x == 0) total = v;
    __syncthreads();
    return total;
}

__device__ __forceinline__ float silu_f(float x) {
    return x / (1.f + __expf(-x));
}

__device__ __forceinline__ void split2v(float f0, float f1,
                                        __nv_bfloat162& hi, __nv_bfloat162& lo) {
    hi = __floats2bfloat162_rn(f0, f1);
    lo = __floats2bfloat162_rn(f0 - __bfloat162float(hi.x), f1 - __bfloat162float(hi.y));
}

__device__ __forceinline__ void mma_bf16(float* c, const uint32_t* a, uint32_t b0, uint32_t b1) {
    asm volatile(
        "mma.sync.aligned.m16n8k16.row.col.f32.bf16.bf16.f32 "
        "{%0,%1,%2,%3}, {%4,%5,%6,%7}, {%8,%9}, {%0,%1,%2,%3};"
        : "+f"(c[0]), "+f"(c[1]), "+f"(c[2]), "+f"(c[3])
        : "r"(a[0]), "r"(a[1]), "r"(a[2]), "r"(a[3]), "r"(b0), "r"(b1));
}

__device__ __forceinline__ void ldsm4(uint32_t* r, uint32_t addr) {
    asm volatile("ldmatrix.sync.aligned.m8n8.x4.shared.b16 {%0,%1,%2,%3}, [%4];"
        : "=r"(r[0]), "=r"(r[1]), "=r"(r[2]), "=r"(r[3]) : "r"(addr));
}

__device__ __forceinline__ void cp16(uint32_t dst, const void* src, int sz) {
    asm volatile("cp.async.cg.shared.global [%0], [%1], 16, %2;"
                 :: "r"(dst), "l"(src), "r"(sz));
}
#define CP_COMMIT() asm volatile("cp.async.commit_group;")
#define CP_WAIT(n)  asm volatile("cp.async.wait_group %0;" :: "n"(n))

// swizzled smem byte offset inside one 128x32 bf16 tile (64B rows)
__device__ __forceinline__ uint32_t sw_off(int row, int chunk) {
    return (uint32_t)(row * 64 + ((chunk ^ ((row >> 1) & 3)) << 4));
}

// ---------------- weight / activation split kernels ----------------
__global__ void __launch_bounds__(256) split_kernel(
    const float* __restrict__ src, __nv_bfloat16* __restrict__ hi,
    __nv_bfloat16* __restrict__ lo, int n4)
{
    int i = blockIdx.x * 256 + threadIdx.x;
    if (i >= n4) return;
    float4 v = ((const float4*)src)[i];
    __nv_bfloat162 h0, l0, h1, l1;
    split2v(v.x, v.y, h0, l0);
    split2v(v.z, v.w, h1, l1);
    ((__nv_bfloat162*)hi)[i * 2]     = h0;
    ((__nv_bfloat162*)hi)[i * 2 + 1] = h1;
    ((__nv_bfloat162*)lo)[i * 2]     = l0;
    ((__nv_bfloat162*)lo)[i * 2 + 1] = l1;
}

// dbl[:, :48] (lda 80) -> compact hi/lo [TOTAL,48]
__global__ void __launch_bounds__(256) split48_kernel(
    const float* __restrict__ src, __nv_bfloat16* __restrict__ hi,
    __nv_bfloat16* __restrict__ lo)
{
    int p = blockIdx.x * 256 + threadIdx.x;      // pair index
    if (p >= TOTAL * 24) return;
    int row = p / 24, cp = p % 24;
    const float* s = src + (size_t)row * 80 + cp * 2;
    __nv_bfloat162 h, l;
    split2v(s[0], s[1], h, l);
    ((__nv_bfloat162*)hi)[row * 24 + cp] = h;
    ((__nv_bfloat162*)lo)[row * 24 + cp] = l;
}

// ---------------- embed gather + rmsnorm (fp32 residual) ----------------
__global__ void __launch_bounds__(256) embed_rms_kernel(
    const int* __restrict__ tokens, const float* __restrict__ embed,
    const float* __restrict__ w, float* __restrict__ out)
{
    const int row = blockIdx.x;
    const float* xr = embed + (size_t)tokens[row] * D_MODEL;
    float s = 0.f;
    for (int i = threadIdx.x; i < D_MODEL; i += 256) { float v = xr[i]; s += v * v; }
    float tot = blockReduceSum(s);
    float r = rsqrtf(tot / D_MODEL + EPS);
    for (int i = threadIdx.x; i < D_MODEL; i += 256)
        out[row * D_MODEL + i] = xr[i] * r * w[i];
}

// ---------------- rmsnorm -> bf16 hi/lo ----------------
__global__ void __launch_bounds__(256) rms_split_kernel(
    const float* __restrict__ x, const float* __restrict__ w,
    __nv_bfloat16* __restrict__ hi, __nv_bfloat16* __restrict__ lo)
{
    const int row = blockIdx.x;
    const float* xr = x + row * D_MODEL;
    float s = 0.f;
    for (int i = threadIdx.x; i < D_MODEL; i += 256) { float v = xr[i]; s += v * v; }
    float tot = blockReduceSum(s);
    float r = rsqrtf(tot / D_MODEL + EPS);
    for (int p = threadIdx.x; p < D_MODEL / 2; p += 256) {
        float2 v = ((const float2*)xr)[p];
        float a = v.x * r * w[p * 2], b = v.y * r * w[p * 2 + 1];
        __nv_bfloat162 h, l;
        split2v(a, b, h, l);
        ((__nv_bfloat162*)hi)[row * (D_MODEL / 2) + p] = h;
        ((__nv_bfloat162*)lo)[row * (D_MODEL / 2) + p] = l;
    }
}

// ---------------- final: rmsnorm(norm_f) then rmsnorm(out_norm) ----------------
__global__ void __launch_bounds__(256) final_kernel(
    const float* __restrict__ x, const float* __restrict__ wf,
    const float* __restrict__ wo, float* __restrict__ out)
{
    const int row = blockIdx.x;
    const float* xr = x + row * D_MODEL;
    float s1 = 0.f, s2 = 0.f;
    for (int i = threadIdx.x; i < D_MODEL; i += 256) {
        float v = xr[i];
        float vw = v * wf[i];
        s1 += v * v;
        s2 += vw * vw;
    }
    float t1 = blockReduceSum(s1);
    float t2 = blockReduceSum(s2);
    float r1 = rsqrtf(t1 / D_MODEL + EPS);
    float m2 = (r1 * r1) * t2 / D_MODEL;
    float r2 = rsqrtf(m2 + EPS);
    for (int i = threadIdx.x; i < D_MODEL; i += 256)
        out[row * D_MODEL + i] = xr[i] * wf[i] * r1 * r2 * wo[i];
}

// ---------------- tensor-core GEMM ----------------
// C[M,N] (op)= A[M,K] * W[N,K]^T, operands pre-split bf16 hi/lo.
// Block 128x128xBK32, 8 warps, warp tile 64x32, 3-term split mma, fp32 acc.
// cp.async 2-stage double buffer, ldmatrix fragments, XOR-swizzled smem.
// epi: 0 = store, 1 = softplus(acc + bias[n]), 2 = C += acc
__device__ __forceinline__ void gemm_load_stage(
    uint32_t stbase, int tid, int m0, int n0, int k0, int M, int N, int K,
    const __nv_bfloat16* __restrict__ Ah, const __nv_bfloat16* __restrict__ Al,
    const __nv_bfloat16* __restrict__ Wh, const __nv_bfloat16* __restrict__ Wl)
{
    #pragma unroll
    for (int half = 0; half < 2; half++) {
        int li = half * 256 + tid;          // 0..511
        int row = li >> 2, c = li & 3;
        int k = k0 + c * 8;
        bool kin = (k < K);
        int kc = kin ? k : 0;
        uint32_t dst = stbase + sw_off(row, c);

        int ar = m0 + row; if (ar >= M) ar = M - 1;
        size_t ao = (size_t)ar * K + kc;
        int szA = kin ? 16 : 0;
        cp16(dst,         Ah + ao, szA);
        cp16(dst + 8192,  Al + ao, szA);

        int br = n0 + row;
        bool bin = (br < N) && kin;
        int brc = (br < N) ? br : 0;
        size_t bo = (size_t)brc * K + kc;
        int szB = bin ? 16 : 0;
        cp16(dst + 16384, Wh + bo, szB);
        cp16(dst + 24576, Wl + bo, szB);
    }
}

__global__ void __launch_bounds__(256) gemm_tc_kernel(
    const __nv_bfloat16* __restrict__ Ah, const __nv_bfloat16* __restrict__ Al,
    const __nv_bfloat16* __restrict__ Wh, const __nv_bfloat16* __restrict__ Wl,
    const float* __restrict__ bias, float* __restrict__ C,
    int M, int N, int K, int epi)
{
    extern __shared__ uint8_t smem[];
    const int tid = threadIdx.x, lane = tid & 31, warp = tid >> 5;
    const int m0 = blockIdx.y * 128, n0 = blockIdx.x * 128;
    const int wm = (warp & 1) * 64, wn = (warp >> 1) * 32;
    const int g = lane >> 2, tg = lane & 3;

    uint32_t sbase = (uint32_t)__cvta_generic_to_shared(smem);

    float acc[4][4][4];
    #pragma unroll
    for (int mi = 0; mi < 4; mi++)
        #pragma unroll
        for (int ni = 0; ni < 4; ni++)
            #pragma unroll
            for (int r = 0; r < 4; r++) acc[mi][ni][r] = 0.f;

    const int KT = (K + 31) >> 5;
    gemm_load_stage(sbase, tid, m0, n0, 0, M, N, K, Ah, Al, Wh, Wl);
    CP_COMMIT();

    for (int kt = 0; kt < KT; kt++) {
        if (kt + 1 < KT) {
            gemm_load_stage(sbase + ((kt + 1) & 1) * 32768, tid, m0, n0,
                            (kt + 1) * 32, M, N, K, Ah, Al, Wh, Wl);
            CP_COMMIT();
            CP_WAIT(1);
        } else {
            CP_WAIT(0);
        }
        __syncthreads();

        uint32_t stb  = sbase + (kt & 1) * 32768;
        uint32_t Ah_b = stb, Al_b = stb + 8192, Bh_b = stb + 16384, Bl_b = stb + 24576;
        const int mat = lane >> 3, mr = lane & 7;

        #pragma unroll
        for (int s = 0; s < 2; s++) {
            // B fragments: two x4 per precision cover 4 n-groups
            uint32_t bh[4][2], bl[4][2];
            #pragma unroll
            for (int pair = 0; pair < 2; pair++) {
                int nrow = wn + pair * 16 + ((mat >> 1) << 3) + mr;
                int chunk = s * 2 + (mat & 1);
                uint32_t off = sw_off(nrow, chunk);
                uint32_t r[4];
                ldsm4(r, Bh_b + off);
                bh[pair * 2][0] = r[0]; bh[pair * 2][1] = r[1];
                bh[pair * 2 + 1][0] = r[2]; bh[pair * 2 + 1][1] = r[3];
                ldsm4(r, Bl_b + off);
                bl[pair * 2][0] = r[0]; bl[pair * 2][1] = r[1];
                bl[pair * 2 + 1][0] = r[2]; bl[pair * 2 + 1][1] = r[3];
            }
            #pragma unroll
            for (int mi = 0; mi < 4; mi++) {
                int arow = wm + mi * 16 + ((mat & 1) << 3) + mr;
                int chunk = s * 2 + (mat >> 1);
                uint32_t off = sw_off(arow, chunk);
                uint32_t ah[4], al[4];
                ldsm4(ah, Ah_b + off);
                ldsm4(al, Al_b + off);
                #pragma unroll
                for (int ni = 0; ni < 4; ni++) {
                    mma_bf16(acc[mi][ni], ah, bh[ni][0], bh[ni][1]);
                    mma_bf16(acc[mi][ni], ah, bl[ni][0], bl[ni][1]);
                    mma_bf16(acc[mi][ni], al, bh[ni][0], bh[ni][1]);
                }
            }
        }
        __syncthreads();
    }

    // ---- epilogue ----
    #pragma unroll
    for (int mi = 0; mi < 4; mi++) {
        int mrow0 = m0 + wm + mi * 16 + g;
        int mrow1 = mrow0 + 8;
        #pragma unroll
        for (int ni = 0; ni < 4; ni++) {
            int n = n0 + wn + ni * 8 + 2 * tg;
            if (n >= N) continue;
            float* c = acc[mi][ni];
            if (epi == 1) {
                float b0 = bias[n], b1 = bias[n + 1];
                #pragma unroll
                for (int r = 0; r < 4; r++) {
                    float v = c[r] + ((r & 1) ? b1 : b0);
                    c[r] = (v > 20.f) ? v : log1pf(__expf(v));
                }
            }
            if (mrow0 < M) {
                size_t b = (size_t)mrow0 * N + n;
                if (epi == 2) { C[b] += c[0]; C[b + 1] += c[1]; }
                else          { C[b]  = c[0]; C[b + 1]  = c[1]; }
            }
            if (mrow1 < M) {
                size_t b = (size_t)mrow1 * N + n;
                if (epi == 2) { C[b] += c[2]; C[b + 1] += c[3]; }
                else          { C[b]  = c[2]; C[b + 1]  = c[3]; }
            }
        }
    }
}

// ---------------- causal depthwise conv (k=4) + bias + silu (+ split) ----------------
__global__ void __launch_bounds__(256) conv_kernel(
    const float* __restrict__ xz, const float* __restrict__ cw,
    const float* __restrict__ cb, float* __restrict__ xc,
    __nv_bfloat16* __restrict__ xc_hi, __nv_bfloat16* __restrict__ xc_lo)
{
    int p = blockIdx.x * 256 + threadIdx.x;          // channel-pair index
    if (p >= TOTAL * (D_INNER / 2)) return;
    int t = p / (D_INNER / 2);
    int i = (p - t * (D_INNER / 2)) * 2;
    int t0 = 0;
    #pragma unroll
    for (int s = 1; s < NSUBJ; s++)
        if (t >= c_offsets[s]) t0 = c_offsets[s];

    float o[2];
    #pragma unroll
    for (int u = 0; u < 2; u++) {
        int ch = i + u;
        float w0 = cw[ch * 4 + 0], w1 = cw[ch * 4 + 1], w2 = cw[ch * 4 + 2], w3 = cw[ch * 4 + 3];
        float acc = cb[ch] + w3 * xz[(size_t)t * (2 * D_INNER) + ch];
        if (t - 1 >= t0) acc = fmaf(w2, xz[(size_t)(t - 1) * (2 * D_INNER) + ch], acc);
        if (t - 2 >= t0) acc = fmaf(w1, xz[(size_t)(t - 2) * (2 * D_INNER) + ch], acc);
        if (t - 3 >= t0) acc = fmaf(w0, xz[(size_t)(t - 3) * (2 * D_INNER) + ch], acc);
        o[u] = silu_f(acc);
    }
    ((float2*)xc)[p] = make_float2(o[0], o[1]);
    __nv_bfloat162 h, l;
    split2v(o[0], o[1], h, l);
    ((__nv_bfloat162*)xc_hi)[p] = h;
    ((__nv_bfloat162*)xc_lo)[p] = l;
}

// ---------------- selective scan (+ D skip + silu(z) gate), split output ----------------
__global__ void __launch_bounds__(256) scan_kernel(
    const float* __restrict__ xc, const float* __restrict__ dt,
    const float* __restrict__ dbl, const float* __restrict__ xz,
    const float* __restrict__ A_log, const float* __restrict__ Dp,
    __nv_bfloat16* __restrict__ y_hi, __nv_bfloat16* __restrict__ y_lo)
{
    const int subj = blockIdx.y;
    const int d0 = blockIdx.x * 16;
    const int off = c_offsets[subj];
    const int L = c_offsets[subj + 1] - off;
    const int tid = threadIdx.x;
    const int dl = tid >> 4;
    const int n  = tid & 15;
    const int d  = d0 + dl;

    const float Acoef = -__expf(A_log[d * D_STATE + n]);
    const float Dv = Dp[d];
    float hc = 0.f;

    __shared__ float sh_dt[64][16], sh_x[64][16], sh_z[64][16], sh_B[64][16], sh_C[64][16];

    for (int tb = 0; tb < L; tb += 64) {
        int nsteps = min(64, L - tb);
        for (int idx = tid; idx < 64 * 16; idx += 256) {
            int tl = idx >> 4, dd = idx & 15;
            if (tl < nsteps) {
                int t = off + tb + tl;
                sh_dt[tl][dd] = dt[(size_t)t * D_INNER + d0 + dd];
                sh_x [tl][dd] = xc[(size_t)t * D_INNER + d0 + dd];
                sh_z [tl][dd] = xz[(size_t)t * (2 * D_INNER) + D_INNER + d0 + dd];
                sh_B [tl][dd] = dbl[(size_t)t * 80 + DT_RANK + dd];
                sh_C [tl][dd] = dbl[(size_t)t * 80 + DT_RANK + D_STATE + dd];
            }
        }
        __syncthreads();
        for (int s = 0; s < nsteps; s++) {
            float dtv = sh_dt[s][dl];
            float xv  = sh_x[s][dl];
            float dA = __expf(dtv * Acoef);
            hc = fmaf(dA, hc, (dtv * xv) * sh_B[s][n]);
            float p = hc * sh_C[s][n];
            p += __shfl_xor_sync(0xffffffffu, p, 1);
            p += __shfl_xor_sync(0xffffffffu, p, 2);
            p += __shfl_xor_sync(0xffffffffu, p, 4);
            p += __shfl_xor_sync(0xffffffffu, p, 8);
            if (n == 0) {
                float yv = p + xv * Dv;
                yv *= silu_f(sh_z[s][dl]);
                __nv_bfloat16 h = __float2bfloat16_rn(yv);
                __nv_bfloat16 l = __float2bfloat16_rn(yv - __bfloat162float(h));
                size_t o = (size_t)(off + tb + s) * D_INNER + d;
                y_hi[o] = h;
                y_lo[o] = l;
            }
        }
        __syncthreads();
    }
}

// ---------------- launch ----------------
extern "C" void kernel_launch(void* const* d_in, const int* in_sizes, int n_in,
                              void* d_out, int out_size) {
    const int*   tokens     = (const int*)  d_in[0];
    const float* embed      = (const float*)d_in[1];
    const float* in_norm_w  = (const float*)d_in[2];
    const float* out_norm_w = (const float*)d_in[3];
    const float* norm_w     = (const float*)d_in[4];
    const float* in_proj_w  = (const float*)d_in[5];
    const float* conv_w     = (const float*)d_in[6];
    const float* conv_b     = (const float*)d_in[7];
    const float* x_proj_w   = (const float*)d_in[8];
    const float* dt_proj_w  = (const float*)d_in[9];
    const float* dt_proj_b  = (const float*)d_in[10];
    const float* A_log      = (const float*)d_in[11];
    const float* D_param    = (const float*)d_in[12];
    const float* out_proj_w = (const float*)d_in[13];
    const float* norm_f_w   = (const float*)d_in[14];
    float* out = (float*)d_out;

    float *h, *xz, *xc, *dbl, *dt;
    __nv_bfloat16 *hn_hi, *hn_lo, *xc_hi, *xc_lo, *db_hi, *db_lo, *y_hi, *y_lo;
    __nv_bfloat16 *ip_hi, *ip_lo, *xp_hi, *xp_lo, *dw_hi, *dw_lo, *op_hi, *op_lo;
    cudaGetSymbolAddress((void**)&h,   g_h);
    cudaGetSymbolAddress((void**)&xz,  g_xz);
    cudaGetSymbolAddress((void**)&xc,  g_xc);
    cudaGetSymbolAddress((void**)&dbl, g_dbl);
    cudaGetSymbolAddress((void**)&dt,  g_dt);
    cudaGetSymbolAddress((void**)&hn_hi, g_hn_hi); cudaGetSymbolAddress((void**)&hn_lo, g_hn_lo);
    cudaGetSymbolAddress((void**)&xc_hi, g_xc_hi); cudaGetSymbolAddress((void**)&xc_lo, g_xc_lo);
    cudaGetSymbolAddress((void**)&db_hi, g_db_hi); cudaGetSymbolAddress((void**)&db_lo, g_db_lo);
    cudaGetSymbolAddress((void**)&y_hi,  g_y_hi);  cudaGetSymbolAddress((void**)&y_lo,  g_y_lo);
    cudaGetSymbolAddress((void**)&ip_hi, g_ip_hi); cudaGetSymbolAddress((void**)&ip_lo, g_ip_lo);
    cudaGetSymbolAddress((void**)&xp_hi, g_xp_hi); cudaGetSymbolAddress((void**)&xp_lo, g_xp_lo);
    cudaGetSymbolAddress((void**)&dw_hi, g_dw_hi); cudaGetSymbolAddress((void**)&dw_lo, g_dw_lo);
    cudaGetSymbolAddress((void**)&op_hi, g_op_hi); cudaGetSymbolAddress((void**)&op_lo, g_op_lo);

    cudaFuncSetAttribute(gemm_tc_kernel, cudaFuncAttributeMaxDynamicSharedMemorySize, 65536);

    const int MB = (TOTAL + 127) / 128;   // 54
    const int SMEM = 65536;

    // one-time per launch: split all weights to bf16 hi/lo
    split_kernel<<<(N_LAYERS * IPW_N / 4 + 255) / 256, 256>>>(in_proj_w,  ip_hi, ip_lo, N_LAYERS * IPW_N / 4);
    split_kernel<<<(N_LAYERS * XPW_N / 4 + 255) / 256, 256>>>(x_proj_w,   xp_hi, xp_lo, N_LAYERS * XPW_N / 4);
    split_kernel<<<(N_LAYERS * DTW_N / 4 + 255) / 256, 256>>>(dt_proj_w,  dw_hi, dw_lo, N_LAYERS * DTW_N / 4);
    split_kernel<<<(N_LAYERS * OPW_N / 4 + 255) / 256, 256>>>(out_proj_w, op_hi, op_lo, N_LAYERS * OPW_N / 4);

    embed_rms_kernel<<<TOTAL, 256>>>(tokens, embed, in_norm_w, h);

    for (int l = 0; l < N_LAYERS; l++) {
        rms_split_kernel<<<TOTAL, 256>>>(h, norm_w + l * D_MODEL, hn_hi, hn_lo);

        // xz = hn @ in_proj_w^T   [TOTAL, 3072]
        gemm_tc_kernel<<<dim3(2 * D_INNER / 128, MB), 256, SMEM>>>(
            hn_hi, hn_lo, ip_hi + (size_t)l * IPW_N, ip_lo + (size_t)l * IPW_N,
            nullptr, xz, TOTAL, 2 * D_INNER, D_MODEL, 0);

        conv_kernel<<<(TOTAL * D_INNER / 2 + 255) / 256, 256>>>(
            xz, conv_w + (size_t)l * D_INNER * 4, conv_b + (size_t)l * D_INNER,
            xc, xc_hi, xc_lo);

        // dbl = xc @ x_proj_w^T   [TOTAL, 80]
        gemm_tc_kernel<<<dim3(1, MB), 256, SMEM>>>(
            xc_hi, xc_lo, xp_hi + (size_t)l * XPW_N, xp_lo + (size_t)l * XPW_N,
            nullptr, dbl, TOTAL, 80, D_INNER, 0);

        split48_kernel<<<(TOTAL * 24 + 255) / 256, 256>>>(dbl, db_hi, db_lo);

        // dt = softplus(dbl[:, :48] @ dt_proj_w^T + b)   [TOTAL, 1536]
        gemm_tc_kernel<<<dim3(D_INNER / 128, MB), 256, SMEM>>>(
            db_hi, db_lo, dw_hi + (size_t)l * DTW_N, dw_lo + (size_t)l * DTW_N,
            dt_proj_b + (size_t)l * D_INNER, dt, TOTAL, D_INNER, DT_RANK, 1);

        scan_kernel<<<dim3(D_INNER / 16, NSUBJ), 256>>>(
            xc, dt, dbl, xz,
            A_log + (size_t)l * D_INNER * D_STATE, D_param + (size_t)l * D_INNER,
            y_hi, y_lo);

        // h += y @ out_proj_w^T   [TOTAL, 768]
        gemm_tc_kernel<<<dim3(D_MODEL / 128, MB), 256, SMEM>>>(
            y_hi, y_lo, op_hi + (size_t)l * OPW_N, op_lo + (size_t)l * OPW_N,
            nullptr, h, TOTAL, D_MODEL, D_INNER, 2);
    }

    final_kernel<<<TOTAL, 256>>>(h, norm_f_w, out_norm_w, out);
}